// round 2
// baseline (speedup 1.0000x reference)
#include <cuda_runtime.h>
#include <math.h>

#define BB      4
#define SS      1024
#define DD      512
#define HH      8
#define DEP     64
#define DFFN    2048
#define NLAYERS 4

#define XN  (BB*SS*DD)       /* 2097152  */
#define AWN (BB*HH*SS*SS)    /* 33554432 */

// ---------------- device scratch (no allocation allowed) ----------------
__device__ float g_x   [XN];
__device__ float g_q   [XN];
__device__ float g_k   [XN];
__device__ float g_v   [XN];
__device__ float g_att [XN];
__device__ float g_y   [XN];
__device__ float g_o1  [XN];
__device__ float g_hbuf[BB*SS*DFFN];
__device__ float g_e   [AWN];          // logits, then exp(logits - max), in place
__device__ int   g_maxbits[BB*HH];
__device__ float g_sum    [BB*HH];
__device__ float g_rowcount;

// ---------------- helpers ----------------
__device__ __forceinline__ int f2o(float f) {
    int i = __float_as_int(f);
    return (i >= 0) ? i : (i ^ 0x7FFFFFFF);
}
__device__ __forceinline__ float o2f(int i) {
    return __int_as_float((i >= 0) ? i : (i ^ 0x7FFFFFFF));
}

// ---------------- row_count = count_nonzero(protok[0, :]) ----------------
__global__ void rowcount_kernel(const int* __restrict__ protok) {
    __shared__ int red[32];
    int t = threadIdx.x;                 // 1024 threads
    int c = (protok[t] != 0) ? 1 : 0;
    #pragma unroll
    for (int o = 16; o; o >>= 1) c += __shfl_xor_sync(0xffffffffu, c, o);
    if ((t & 31) == 0) red[t >> 5] = c;
    __syncthreads();
    if (t < 32) {
        int v = red[t];
        #pragma unroll
        for (int o = 16; o; o >>= 1) v += __shfl_xor_sync(0xffffffffu, v, o);
        if (t == 0) g_rowcount = (float)v;
    }
}

__global__ void init_reduce_kernel() {
    int t = threadIdx.x;
    if (t < BB * HH) { g_maxbits[t] = (int)0x80000000; g_sum[t] = 0.0f; }
}

__global__ void copy_kernel(float* __restrict__ dst, const float* __restrict__ src, int n) {
    int i = blockIdx.x * blockDim.x + threadIdx.x;
    int stride = gridDim.x * blockDim.x;
    for (; i < n; i += stride) dst[i] = src[i];
}

// ---------------- generic row-major GEMM: C = A[M,K] @ W[K,N] (+bias,+resid,relu,head-split) ----------------
// 64x64 tile, k-chunk 16, 256 threads, 4x4 outputs/thread with stride-16 col/row mapping.
__global__ __launch_bounds__(256) void gemm_rm(
    const float* __restrict__ A, const float* __restrict__ W,
    const float* __restrict__ bias, const float* __restrict__ R,
    float* __restrict__ C, int M, int N, int K, int relu, int headsplit)
{
    __shared__ float As[64][17];
    __shared__ float Ws[16][65];
    int tx = threadIdx.x, ty = threadIdx.y;
    int tid = ty * 16 + tx;
    int m0 = blockIdx.y << 6, n0 = blockIdx.x << 6;
    float acc[4][4] = {};

    for (int k0 = 0; k0 < K; k0 += 16) {
        #pragma unroll
        for (int i = 0; i < 4; i++) {
            int l = tid + 256 * i; int r = l >> 4, kk = l & 15;
            As[r][kk] = A[(size_t)(m0 + r) * K + k0 + kk];
        }
        #pragma unroll
        for (int i = 0; i < 4; i++) {
            int l = tid + 256 * i; int kk = l >> 6, n = l & 63;
            Ws[kk][n] = W[(size_t)(k0 + kk) * N + n0 + n];
        }
        __syncthreads();
        #pragma unroll
        for (int kk = 0; kk < 16; kk++) {
            float a0 = As[ty][kk], a1 = As[ty + 16][kk], a2 = As[ty + 32][kk], a3 = As[ty + 48][kk];
            float b0 = Ws[kk][tx], b1 = Ws[kk][tx + 16], b2 = Ws[kk][tx + 32], b3 = Ws[kk][tx + 48];
            acc[0][0] += a0 * b0; acc[0][1] += a0 * b1; acc[0][2] += a0 * b2; acc[0][3] += a0 * b3;
            acc[1][0] += a1 * b0; acc[1][1] += a1 * b1; acc[1][2] += a1 * b2; acc[1][3] += a1 * b3;
            acc[2][0] += a2 * b0; acc[2][1] += a2 * b1; acc[2][2] += a2 * b2; acc[2][3] += a2 * b3;
            acc[3][0] += a3 * b0; acc[3][1] += a3 * b1; acc[3][2] += a3 * b2; acc[3][3] += a3 * b3;
        }
        __syncthreads();
    }

    #pragma unroll
    for (int a = 0; a < 4; a++) {
        #pragma unroll
        for (int c = 0; c < 4; c++) {
            int m = m0 + ty + 16 * a, n = n0 + tx + 16 * c;
            float v = acc[a][c] + bias[n];
            if (R) v += R[(size_t)m * N + n];
            if (relu) v = fmaxf(v, 0.0f);
            if (headsplit) {
                int bb = m >> 10, s = m & 1023, hh = n >> 6, dd = n & 63;
                C[(((size_t)(bb * HH + hh) << 10) | (size_t)s) * DEP + dd] = v;
            } else {
                C[(size_t)m * N + n] = v;
            }
        }
    }
}

// ---------------- logits: per (b,h): (Q K^T + mask*-1e9) / 8, fused block-max ----------------
__global__ __launch_bounds__(256) void logits_kernel(const float* __restrict__ mask) {
    __shared__ float Qs[64][65];
    __shared__ float Ks[64][65];
    __shared__ float red[8];
    int tx = threadIdx.x, ty = threadIdx.y;
    int tid = ty * 16 + tx;
    int bh = blockIdx.z; int bi = bh >> 3;
    int i0 = blockIdx.y << 6, j0 = blockIdx.x << 6;
    const float* q = g_q + (size_t)bh * SS * DEP;
    const float* k = g_k + (size_t)bh * SS * DEP;

    #pragma unroll
    for (int i = 0; i < 16; i++) {
        int l = tid + 256 * i; int r = l >> 6, c = l & 63;
        Qs[r][c] = q[(size_t)(i0 + r) * DEP + c];
        Ks[r][c] = k[(size_t)(j0 + r) * DEP + c];
    }
    __syncthreads();

    float acc[4][4] = {};
    #pragma unroll
    for (int kk = 0; kk < 64; kk++) {
        float a0 = Qs[ty][kk], a1 = Qs[ty + 16][kk], a2 = Qs[ty + 32][kk], a3 = Qs[ty + 48][kk];
        float b0 = Ks[tx][kk], b1 = Ks[tx + 16][kk], b2 = Ks[tx + 32][kk], b3 = Ks[tx + 48][kk];
        acc[0][0] += a0 * b0; acc[0][1] += a0 * b1; acc[0][2] += a0 * b2; acc[0][3] += a0 * b3;
        acc[1][0] += a1 * b0; acc[1][1] += a1 * b1; acc[1][2] += a1 * b2; acc[1][3] += a1 * b3;
        acc[2][0] += a2 * b0; acc[2][1] += a2 * b1; acc[2][2] += a2 * b2; acc[2][3] += a2 * b3;
        acc[3][0] += a3 * b0; acc[3][1] += a3 * b1; acc[3][2] += a3 * b2; acc[3][3] += a3 * b3;
    }

    float* out = g_e + (size_t)bh * SS * SS;
    float lmax = -INFINITY;
    #pragma unroll
    for (int a = 0; a < 4; a++) {
        #pragma unroll
        for (int c = 0; c < 4; c++) {
            int i = i0 + ty + 16 * a, j = j0 + tx + 16 * c;
            float v = (acc[a][c] + mask[((size_t)bi * SS + i) * SS + j] * (-1e9f)) * 0.125f;
            out[(size_t)i * SS + j] = v;
            lmax = fmaxf(lmax, v);
        }
    }
    #pragma unroll
    for (int o = 16; o; o >>= 1) lmax = fmaxf(lmax, __shfl_xor_sync(0xffffffffu, lmax, o));
    if ((tid & 31) == 0) red[tid >> 5] = lmax;
    __syncthreads();
    if (tid == 0) {
        float m = red[0];
        #pragma unroll
        for (int w = 1; w < 8; w++) m = fmaxf(m, red[w]);
        atomicMax(&g_maxbits[bh], f2o(m));
    }
}

// ---------------- exp in place + partial sums ----------------
__global__ __launch_bounds__(256) void exp_kernel() {
    __shared__ float red[8];
    int bh = blockIdx.y;
    float mx = o2f(g_maxbits[bh]);
    size_t base = (size_t)bh * SS * SS + (size_t)blockIdx.x * 16384;
    int t = threadIdx.x;
    float lsum = 0.0f;
    #pragma unroll
    for (int i = 0; i < 64; i++) {
        size_t idx = base + t + 256 * i;
        float e = expf(g_e[idx] - mx);
        g_e[idx] = e;
        lsum += e;
    }
    #pragma unroll
    for (int o = 16; o; o >>= 1) lsum += __shfl_xor_sync(0xffffffffu, lsum, o);
    if ((t & 31) == 0) red[t >> 5] = lsum;
    __syncthreads();
    if (t == 0) {
        float s = 0.0f;
        #pragma unroll
        for (int w = 0; w < 8; w++) s += red[w];
        atomicAdd(&g_sum[bh], s);
    }
}

// ---------------- out[b,h,j,d] = (row_count/Z) * sum_i e[i,j] v[i,d] ; write [B,S,D] concat layout ----------------
__global__ __launch_bounds__(256) void attv_kernel() {
    __shared__ float Es[32][65];
    __shared__ float Vs[32][65];
    int tx = threadIdx.x, ty = threadIdx.y;
    int tid = ty * 16 + tx;
    int bh = blockIdx.z; int bat = bh >> 3, hh = bh & 7;
    int j0 = blockIdx.x << 6;
    const float* e = g_e + (size_t)bh * SS * SS;
    const float* v = g_v + (size_t)bh * SS * DEP;
    float acc[4][4] = {};

    for (int i0 = 0; i0 < SS; i0 += 32) {
        #pragma unroll
        for (int i = 0; i < 8; i++) {
            int l = tid + 256 * i; int r = l >> 6, c = l & 63;
            Es[r][c] = e[(size_t)(i0 + r) * SS + j0 + c];
            Vs[r][c] = v[(size_t)(i0 + r) * DEP + c];
        }
        __syncthreads();
        #pragma unroll
        for (int kk = 0; kk < 32; kk++) {
            float a0 = Es[kk][ty], a1 = Es[kk][ty + 16], a2 = Es[kk][ty + 32], a3 = Es[kk][ty + 48];
            float b0 = Vs[kk][tx], b1 = Vs[kk][tx + 16], b2 = Vs[kk][tx + 32], b3 = Vs[kk][tx + 48];
            acc[0][0] += a0 * b0; acc[0][1] += a0 * b1; acc[0][2] += a0 * b2; acc[0][3] += a0 * b3;
            acc[1][0] += a1 * b0; acc[1][1] += a1 * b1; acc[1][2] += a1 * b2; acc[1][3] += a1 * b3;
            acc[2][0] += a2 * b0; acc[2][1] += a2 * b1; acc[2][2] += a2 * b2; acc[2][3] += a2 * b3;
            acc[3][0] += a3 * b0; acc[3][1] += a3 * b1; acc[3][2] += a3 * b2; acc[3][3] += a3 * b3;
        }
        __syncthreads();
    }

    float scale = g_rowcount / g_sum[bh];
    #pragma unroll
    for (int a = 0; a < 4; a++) {
        #pragma unroll
        for (int c = 0; c < 4; c++) {
            int j = j0 + ty + 16 * a, d = tx + 16 * c;
            g_att[((size_t)bat * SS + j) * DD + hh * DEP + d] = acc[a][c] * scale;
        }
    }
}

// ---------------- LayerNorm over last dim (512), eps inside sqrt ----------------
__global__ __launch_bounds__(128) void ln_kernel(
    const float* __restrict__ in, const float* __restrict__ gam,
    const float* __restrict__ bet, float* __restrict__ out)
{
    __shared__ float red[4];
    __shared__ float bc;
    int row = blockIdx.x, t = threadIdx.x;
    const float* rp = in + (size_t)row * DD;
    float v0 = rp[t], v1 = rp[t + 128], v2 = rp[t + 256], v3 = rp[t + 384];
    float s = v0 + v1 + v2 + v3;
    #pragma unroll
    for (int o = 16; o; o >>= 1) s += __shfl_xor_sync(0xffffffffu, s, o);
    if ((t & 31) == 0) red[t >> 5] = s;
    __syncthreads();
    if (t == 0) bc = (red[0] + red[1] + red[2] + red[3]) * (1.0f / 512.0f);
    __syncthreads();
    float mean = bc;
    float d0 = v0 - mean, d1 = v1 - mean, d2 = v2 - mean, d3 = v3 - mean;
    float ss = d0 * d0 + d1 * d1 + d2 * d2 + d3 * d3;
    #pragma unroll
    for (int o = 16; o; o >>= 1) ss += __shfl_xor_sync(0xffffffffu, ss, o);
    __syncthreads();
    if ((t & 31) == 0) red[t >> 5] = ss;
    __syncthreads();
    if (t == 0) bc = (red[0] + red[1] + red[2] + red[3]) * (1.0f / 512.0f);
    __syncthreads();
    float inv = rsqrtf(bc + 1e-9f);
    float* op = out + (size_t)row * DD;
    op[t]       = gam[t]       * d0 * inv + bet[t];
    op[t + 128] = gam[t + 128] * d1 * inv + bet[t + 128];
    op[t + 256] = gam[t + 256] * d2 * inv + bet[t + 256];
    op[t + 384] = gam[t + 384] * d3 * inv + bet[t + 384];
}

// ---------------- final aw write: normalized * row_count ----------------
__global__ __launch_bounds__(256) void awout_kernel(float* __restrict__ out) {
    size_t i = (size_t)blockIdx.x * 256 + threadIdx.x;
    int bh = (int)(i >> 20);                   // S*S = 2^20
    out[i] = g_e[i] * (g_rowcount / g_sum[bh]);
}

// ---------------- launch ----------------
extern "C" void kernel_launch(void* const* d_in, const int* in_sizes, int n_in,
                              void* d_out, int out_size)
{
    const float* x_in  = (const float*)d_in[0];
    const float* mask  = (const float*)d_in[1];
    const int*   protok= (const int*)  d_in[2];
    const float* wq_w  = (const float*)d_in[3];
    const float* wq_b  = (const float*)d_in[4];
    const float* wk_w  = (const float*)d_in[5];
    const float* wk_b  = (const float*)d_in[6];
    const float* wv_w  = (const float*)d_in[7];
    const float* wv_b  = (const float*)d_in[8];
    const float* wo_w  = (const float*)d_in[9];
    const float* wo_b  = (const float*)d_in[10];
    const float* w1    = (const float*)d_in[11];
    const float* b1    = (const float*)d_in[12];
    const float* w2    = (const float*)d_in[13];
    const float* b2    = (const float*)d_in[14];
    const float* ln1g  = (const float*)d_in[15];
    const float* ln1b  = (const float*)d_in[16];
    const float* ln2g  = (const float*)d_in[17];
    const float* ln2b  = (const float*)d_in[18];

    float *px, *pq, *pk, *pv, *patt, *py, *po1, *ph;
    cudaGetSymbolAddress((void**)&px,   g_x);
    cudaGetSymbolAddress((void**)&pq,   g_q);
    cudaGetSymbolAddress((void**)&pk,   g_k);
    cudaGetSymbolAddress((void**)&pv,   g_v);
    cudaGetSymbolAddress((void**)&patt, g_att);
    cudaGetSymbolAddress((void**)&py,   g_y);
    cudaGetSymbolAddress((void**)&po1,  g_o1);
    cudaGetSymbolAddress((void**)&ph,   g_hbuf);

    dim3 blk(16, 16);

    rowcount_kernel<<<1, 1024>>>(protok);
    copy_kernel<<<2048, 256>>>(px, x_in, XN);

    for (int l = 0; l < NLAYERS; l++) {
        gemm_rm<<<dim3(8, 64),  blk>>>(px,   wq_w, wq_b, nullptr, pq, BB*SS, DD,   DD,   0, 1);
        gemm_rm<<<dim3(8, 64),  blk>>>(px,   wk_w, wk_b, nullptr, pk, BB*SS, DD,   DD,   0, 1);
        gemm_rm<<<dim3(8, 64),  blk>>>(px,   wv_w, wv_b, nullptr, pv, BB*SS, DD,   DD,   0, 1);
        init_reduce_kernel<<<1, 64>>>();
        logits_kernel<<<dim3(16, 16, 32), blk>>>(mask);
        exp_kernel<<<dim3(64, 32), 256>>>();
        attv_kernel<<<dim3(16, 1, 32), blk>>>();
        gemm_rm<<<dim3(8, 64),  blk>>>(patt, wo_w, wo_b, px,      py, BB*SS, DD,   DD,   0, 0);
        ln_kernel<<<BB*SS, 128>>>(py, ln1g, ln1b, po1);
        gemm_rm<<<dim3(32, 64), blk>>>(po1,  w1,   b1,   nullptr, ph, BB*SS, DFFN, DD,   1, 0);
        gemm_rm<<<dim3(8, 64),  blk>>>(ph,   w2,   b2,   po1,     py, BB*SS, DD,   DFFN, 0, 0);
        ln_kernel<<<BB*SS, 128>>>(py, ln2g, ln2b, px);
    }

    if (out_size >= XN) {
        copy_kernel<<<2048, 256>>>((float*)d_out, px, XN);
    }
    if (out_size >= XN + AWN) {
        awout_kernel<<<AWN / 256, 256>>>((float*)d_out + XN);
    }
}

// round 3
// speedup vs baseline: 1.3959x; 1.3959x over previous
#include <cuda_runtime.h>
#include <math.h>
#include <stdint.h>

#define BB      4
#define SS      1024
#define DD      512
#define HH      8
#define DEP     64
#define DFFN    2048
#define NLAYERS 4

#define XN  (BB*SS*DD)       /* 2097152  */
#define AWN (BB*HH*SS*SS)    /* 33554432 */

// ---------------- device scratch (no allocation allowed) ----------------
__device__ float g_x   [XN];
__device__ float g_q   [XN];
__device__ float g_k   [XN];
__device__ float g_v   [XN];
__device__ float g_att [XN];
__device__ float g_y   [XN];
__device__ float g_o1  [XN];
__device__ float g_hbuf[BB*SS*DFFN];
__device__ float g_e   [AWN];          // logits, then exp(logits - max), in place
__device__ int   g_maxbits[BB*HH];
__device__ float g_sum    [BB*HH];
__device__ float g_rowcount;

// ---------------- helpers ----------------
__device__ __forceinline__ int f2o(float f) {
    int i = __float_as_int(f);
    return (i >= 0) ? i : (i ^ 0x7FFFFFFF);
}
__device__ __forceinline__ float o2f(int i) {
    return __int_as_float((i >= 0) ? i : (i ^ 0x7FFFFFFF));
}
__device__ __forceinline__ uint32_t f2tf(float f) {
    uint32_t u;
    asm("cvt.rna.tf32.f32 %0, %1;" : "=r"(u) : "f"(f));
    return u;
}
__device__ __forceinline__ void mma_tf32(float* c, const uint32_t* a, const uint32_t* b) {
    asm volatile(
        "mma.sync.aligned.m16n8k8.row.col.f32.tf32.tf32.f32 "
        "{%0,%1,%2,%3}, {%4,%5,%6,%7}, {%8,%9}, {%0,%1,%2,%3};\n"
        : "+f"(c[0]), "+f"(c[1]), "+f"(c[2]), "+f"(c[3])
        : "r"(a[0]), "r"(a[1]), "r"(a[2]), "r"(a[3]), "r"(b[0]), "r"(b[1]));
}

// ---------------- row_count = count_nonzero(protok[0, :]) ----------------
__global__ void rowcount_kernel(const int* __restrict__ protok) {
    __shared__ int red[32];
    int t = threadIdx.x;                 // 1024 threads
    int c = (protok[t] != 0) ? 1 : 0;
    #pragma unroll
    for (int o = 16; o; o >>= 1) c += __shfl_xor_sync(0xffffffffu, c, o);
    if ((t & 31) == 0) red[t >> 5] = c;
    __syncthreads();
    if (t < 32) {
        int v = red[t];
        #pragma unroll
        for (int o = 16; o; o >>= 1) v += __shfl_xor_sync(0xffffffffu, v, o);
        if (t == 0) g_rowcount = (float)v;
    }
}

__global__ void init_reduce_kernel() {
    int t = threadIdx.x;
    if (t < BB * HH) { g_maxbits[t] = (int)0x80000000; g_sum[t] = 0.0f; }
}

__global__ void copy_kernel(float* __restrict__ dst, const float* __restrict__ src, int n) {
    int i = blockIdx.x * blockDim.x + threadIdx.x;
    int stride = gridDim.x * blockDim.x;
    for (; i < n; i += stride) dst[i] = src[i];
}

// ================= tf32 tensor-core GEMM: C = A[M,K] @ W[K,N] =================
// 128x128 block tile, 8 warps (warp tile 64x32), k-chunk 32, m16n8k8 HMMA.
// Epilogue fuses +bias, +residual, relu, head-split scatter.
#define KC 32
#define APITCH 36    /* floats; (36*g+tg)%32 = (4g+tg)%32 -> conflict-free frag loads */
#define BPITCH 136   /* floats; (136*tg+g)%32 = (8tg+g)%32 -> conflict-free frag loads */

__global__ __launch_bounds__(256) void gemm_tf32(
    const float* __restrict__ A, const float* __restrict__ W,
    const float* __restrict__ bias, const float* __restrict__ R,
    float* __restrict__ C, int M, int N, int K, int relu, int headsplit)
{
    __shared__ uint32_t As[128 * APITCH];
    __shared__ uint32_t Bs[KC * BPITCH];

    int tid  = threadIdx.x;
    int warp = tid >> 5, lane = tid & 31;
    int wm = (warp & 1) << 6;      // warp m offset within tile: 0/64
    int wn = (warp >> 1) << 5;     // warp n offset within tile: 0/32/64/96
    int g  = lane >> 2, tg = lane & 3;

    int m0 = blockIdx.y << 7, n0 = blockIdx.x << 7;

    // global->smem mapping (4 float4 each per tensor per stage)
    int arow = tid >> 3,       acol = (tid & 7) << 2;    // A: 128 rows x 32 k
    int brow = tid >> 5,       bcol = (tid & 31) << 2;   // B: 32 k-rows x 128 n

    float acc[4][4][4];
    #pragma unroll
    for (int i = 0; i < 4; i++)
        #pragma unroll
        for (int j = 0; j < 4; j++)
            #pragma unroll
            for (int r = 0; r < 4; r++) acc[i][j][r] = 0.0f;

    for (int k0 = 0; k0 < K; k0 += KC) {
        // ---- load A tile (rows m0.., cols k0..k0+31) ----
        #pragma unroll
        for (int i = 0; i < 4; i++) {
            int r = arow + (i << 5);
            float4 v = *(const float4*)&A[(size_t)(m0 + r) * K + k0 + acol];
            uint32_t* p = &As[r * APITCH + acol];
            p[0] = f2tf(v.x); p[1] = f2tf(v.y); p[2] = f2tf(v.z); p[3] = f2tf(v.w);
        }
        // ---- load B tile (k-rows k0.., cols n0..n0+127) ----
        #pragma unroll
        for (int i = 0; i < 4; i++) {
            int r = brow + (i << 3);
            float4 v = *(const float4*)&W[(size_t)(k0 + r) * N + n0 + bcol];
            uint32_t* p = &Bs[r * BPITCH + bcol];
            p[0] = f2tf(v.x); p[1] = f2tf(v.y); p[2] = f2tf(v.z); p[3] = f2tf(v.w);
        }
        __syncthreads();

        #pragma unroll
        for (int kk = 0; kk < KC; kk += 8) {
            uint32_t af[4][4];
            #pragma unroll
            for (int mt = 0; mt < 4; mt++) {
                int rbase = (wm + (mt << 4) + g) * APITCH + kk + tg;
                af[mt][0] = As[rbase];
                af[mt][1] = As[rbase + 8 * APITCH];
                af[mt][2] = As[rbase + 4];
                af[mt][3] = As[rbase + 8 * APITCH + 4];
            }
            uint32_t bf[4][2];
            #pragma unroll
            for (int nt = 0; nt < 4; nt++) {
                int cbase = (kk + tg) * BPITCH + wn + (nt << 3) + g;
                bf[nt][0] = Bs[cbase];
                bf[nt][1] = Bs[cbase + 4 * BPITCH];
            }
            #pragma unroll
            for (int mt = 0; mt < 4; mt++)
                #pragma unroll
                for (int nt = 0; nt < 4; nt++)
                    mma_tf32(acc[mt][nt], af[mt], bf[nt]);
        }
        __syncthreads();
    }

    // ---- epilogue ----
    #pragma unroll
    for (int mt = 0; mt < 4; mt++) {
        #pragma unroll
        for (int nt = 0; nt < 4; nt++) {
            int m = m0 + wm + (mt << 4) + g;
            int n = n0 + wn + (nt << 3) + (tg << 1);
            #pragma unroll
            for (int half = 0; half < 2; half++) {   // rows m and m+8
                int mm = m + half * 8;
                float2 v;
                v.x = acc[mt][nt][half * 2 + 0] + bias[n];
                v.y = acc[mt][nt][half * 2 + 1] + bias[n + 1];
                if (R) {
                    const float2 rr = *(const float2*)&R[(size_t)mm * N + n];
                    v.x += rr.x; v.y += rr.y;
                }
                if (relu) { v.x = fmaxf(v.x, 0.0f); v.y = fmaxf(v.y, 0.0f); }
                if (headsplit) {
                    int bb = mm >> 10, s = mm & 1023, hh = n >> 6, dd = n & 63;
                    *(float2*)&C[(((size_t)(bb * HH + hh) << 10) | (size_t)s) * DEP + dd] = v;
                } else {
                    *(float2*)&C[(size_t)mm * N + n] = v;
                }
            }
        }
    }
}

// ---------------- logits: per (b,h): (Q K^T + mask*-1e9) / 8, fused block-max ----------------
__global__ __launch_bounds__(256) void logits_kernel(const float* __restrict__ mask) {
    __shared__ float Qs[64][65];
    __shared__ float Ks[64][65];
    __shared__ float red[8];
    int tx = threadIdx.x, ty = threadIdx.y;
    int tid = ty * 16 + tx;
    int bh = blockIdx.z; int bi = bh >> 3;
    int i0 = blockIdx.y << 6, j0 = blockIdx.x << 6;
    const float* q = g_q + (size_t)bh * SS * DEP;
    const float* k = g_k + (size_t)bh * SS * DEP;

    #pragma unroll
    for (int i = 0; i < 16; i++) {
        int l = tid + 256 * i; int r = l >> 6, c = l & 63;
        Qs[r][c] = q[(size_t)(i0 + r) * DEP + c];
        Ks[r][c] = k[(size_t)(j0 + r) * DEP + c];
    }
    __syncthreads();

    float acc[4][4] = {};
    #pragma unroll
    for (int kk = 0; kk < 64; kk++) {
        float a0 = Qs[ty][kk], a1 = Qs[ty + 16][kk], a2 = Qs[ty + 32][kk], a3 = Qs[ty + 48][kk];
        float b0 = Ks[tx][kk], b1 = Ks[tx + 16][kk], b2 = Ks[tx + 32][kk], b3 = Ks[tx + 48][kk];
        acc[0][0] += a0 * b0; acc[0][1] += a0 * b1; acc[0][2] += a0 * b2; acc[0][3] += a0 * b3;
        acc[1][0] += a1 * b0; acc[1][1] += a1 * b1; acc[1][2] += a1 * b2; acc[1][3] += a1 * b3;
        acc[2][0] += a2 * b0; acc[2][1] += a2 * b1; acc[2][2] += a2 * b2; acc[2][3] += a2 * b3;
        acc[3][0] += a3 * b0; acc[3][1] += a3 * b1; acc[3][2] += a3 * b2; acc[3][3] += a3 * b3;
    }

    float* out = g_e + (size_t)bh * SS * SS;
    float lmax = -INFINITY;
    #pragma unroll
    for (int a = 0; a < 4; a++) {
        #pragma unroll
        for (int c = 0; c < 4; c++) {
            int i = i0 + ty + 16 * a, j = j0 + tx + 16 * c;
            float v = (acc[a][c] + mask[((size_t)bi * SS + i) * SS + j] * (-1e9f)) * 0.125f;
            out[(size_t)i * SS + j] = v;
            lmax = fmaxf(lmax, v);
        }
    }
    #pragma unroll
    for (int o = 16; o; o >>= 1) lmax = fmaxf(lmax, __shfl_xor_sync(0xffffffffu, lmax, o));
    if ((tid & 31) == 0) red[tid >> 5] = lmax;
    __syncthreads();
    if (tid == 0) {
        float m = red[0];
        #pragma unroll
        for (int w = 1; w < 8; w++) m = fmaxf(m, red[w]);
        atomicMax(&g_maxbits[bh], f2o(m));
    }
}

// ---------------- exp in place + partial sums ----------------
__global__ __launch_bounds__(256) void exp_kernel() {
    __shared__ float red[8];
    int bh = blockIdx.y;
    float mx = o2f(g_maxbits[bh]);
    size_t base = (size_t)bh * SS * SS + (size_t)blockIdx.x * 16384;
    int t = threadIdx.x;
    float lsum = 0.0f;
    #pragma unroll
    for (int i = 0; i < 64; i++) {
        size_t idx = base + t + 256 * i;
        float e = expf(g_e[idx] - mx);
        g_e[idx] = e;
        lsum += e;
    }
    #pragma unroll
    for (int o = 16; o; o >>= 1) lsum += __shfl_xor_sync(0xffffffffu, lsum, o);
    if ((t & 31) == 0) red[t >> 5] = lsum;
    __syncthreads();
    if (t == 0) {
        float s = 0.0f;
        #pragma unroll
        for (int w = 0; w < 8; w++) s += red[w];
        atomicAdd(&g_sum[bh], s);
    }
}

// ---------------- out[b,h,j,d] = (row_count/Z) * sum_i e[i,j] v[i,d] ; write [B,S,D] concat layout ----------------
__global__ __launch_bounds__(256) void attv_kernel() {
    __shared__ float Es[32][65];
    __shared__ float Vs[32][65];
    int tx = threadIdx.x, ty = threadIdx.y;
    int tid = ty * 16 + tx;
    int bh = blockIdx.z; int bat = bh >> 3, hh = bh & 7;
    int j0 = blockIdx.x << 6;
    const float* e = g_e + (size_t)bh * SS * SS;
    const float* v = g_v + (size_t)bh * SS * DEP;
    float acc[4][4] = {};

    for (int i0 = 0; i0 < SS; i0 += 32) {
        #pragma unroll
        for (int i = 0; i < 8; i++) {
            int l = tid + 256 * i; int r = l >> 6, c = l & 63;
            Es[r][c] = e[(size_t)(i0 + r) * SS + j0 + c];
            Vs[r][c] = v[(size_t)(i0 + r) * DEP + c];
        }
        __syncthreads();
        #pragma unroll
        for (int kk = 0; kk < 32; kk++) {
            float a0 = Es[kk][ty], a1 = Es[kk][ty + 16], a2 = Es[kk][ty + 32], a3 = Es[kk][ty + 48];
            float b0 = Vs[kk][tx], b1 = Vs[kk][tx + 16], b2 = Vs[kk][tx + 32], b3 = Vs[kk][tx + 48];
            acc[0][0] += a0 * b0; acc[0][1] += a0 * b1; acc[0][2] += a0 * b2; acc[0][3] += a0 * b3;
            acc[1][0] += a1 * b0; acc[1][1] += a1 * b1; acc[1][2] += a1 * b2; acc[1][3] += a1 * b3;
            acc[2][0] += a2 * b0; acc[2][1] += a2 * b1; acc[2][2] += a2 * b2; acc[2][3] += a2 * b3;
            acc[3][0] += a3 * b0; acc[3][1] += a3 * b1; acc[3][2] += a3 * b2; acc[3][3] += a3 * b3;
        }
        __syncthreads();
    }

    float scale = g_rowcount / g_sum[bh];
    #pragma unroll
    for (int a = 0; a < 4; a++) {
        #pragma unroll
        for (int c = 0; c < 4; c++) {
            int j = j0 + ty + 16 * a, d = tx + 16 * c;
            g_att[((size_t)bat * SS + j) * DD + hh * DEP + d] = acc[a][c] * scale;
        }
    }
}

// ---------------- LayerNorm over last dim (512), eps inside sqrt ----------------
__global__ __launch_bounds__(128) void ln_kernel(
    const float* __restrict__ in, const float* __restrict__ gam,
    const float* __restrict__ bet, float* __restrict__ out)
{
    __shared__ float red[4];
    __shared__ float bc;
    int row = blockIdx.x, t = threadIdx.x;
    const float* rp = in + (size_t)row * DD;
    float v0 = rp[t], v1 = rp[t + 128], v2 = rp[t + 256], v3 = rp[t + 384];
    float s = v0 + v1 + v2 + v3;
    #pragma unroll
    for (int o = 16; o; o >>= 1) s += __shfl_xor_sync(0xffffffffu, s, o);
    if ((t & 31) == 0) red[t >> 5] = s;
    __syncthreads();
    if (t == 0) bc = (red[0] + red[1] + red[2] + red[3]) * (1.0f / 512.0f);
    __syncthreads();
    float mean = bc;
    float d0 = v0 - mean, d1 = v1 - mean, d2 = v2 - mean, d3 = v3 - mean;
    float ss = d0 * d0 + d1 * d1 + d2 * d2 + d3 * d3;
    #pragma unroll
    for (int o = 16; o; o >>= 1) ss += __shfl_xor_sync(0xffffffffu, ss, o);
    __syncthreads();
    if ((t & 31) == 0) red[t >> 5] = ss;
    __syncthreads();
    if (t == 0) bc = (red[0] + red[1] + red[2] + red[3]) * (1.0f / 512.0f);
    __syncthreads();
    float inv = rsqrtf(bc + 1e-9f);
    float* op = out + (size_t)row * DD;
    op[t]       = gam[t]       * d0 * inv + bet[t];
    op[t + 128] = gam[t + 128] * d1 * inv + bet[t + 128];
    op[t + 256] = gam[t + 256] * d2 * inv + bet[t + 256];
    op[t + 384] = gam[t + 384] * d3 * inv + bet[t + 384];
}

// ---------------- final aw write: normalized * row_count ----------------
__global__ __launch_bounds__(256) void awout_kernel(float* __restrict__ out) {
    size_t i = (size_t)blockIdx.x * 256 + threadIdx.x;
    int bh = (int)(i >> 20);                   // S*S = 2^20
    out[i] = g_e[i] * (g_rowcount / g_sum[bh]);
}

// ---------------- launch ----------------
extern "C" void kernel_launch(void* const* d_in, const int* in_sizes, int n_in,
                              void* d_out, int out_size)
{
    const float* x_in  = (const float*)d_in[0];
    const float* mask  = (const float*)d_in[1];
    const int*   protok= (const int*)  d_in[2];
    const float* wq_w  = (const float*)d_in[3];
    const float* wq_b  = (const float*)d_in[4];
    const float* wk_w  = (const float*)d_in[5];
    const float* wk_b  = (const float*)d_in[6];
    const float* wv_w  = (const float*)d_in[7];
    const float* wv_b  = (const float*)d_in[8];
    const float* wo_w  = (const float*)d_in[9];
    const float* wo_b  = (const float*)d_in[10];
    const float* w1    = (const float*)d_in[11];
    const float* b1    = (const float*)d_in[12];
    const float* w2    = (const float*)d_in[13];
    const float* b2    = (const float*)d_in[14];
    const float* ln1g  = (const float*)d_in[15];
    const float* ln1b  = (const float*)d_in[16];
    const float* ln2g  = (const float*)d_in[17];
    const float* ln2b  = (const float*)d_in[18];

    float *px, *pq, *pk, *pv, *patt, *py, *po1, *ph;
    cudaGetSymbolAddress((void**)&px,   g_x);
    cudaGetSymbolAddress((void**)&pq,   g_q);
    cudaGetSymbolAddress((void**)&pk,   g_k);
    cudaGetSymbolAddress((void**)&pv,   g_v);
    cudaGetSymbolAddress((void**)&patt, g_att);
    cudaGetSymbolAddress((void**)&py,   g_y);
    cudaGetSymbolAddress((void**)&po1,  g_o1);
    cudaGetSymbolAddress((void**)&ph,   g_hbuf);

    dim3 blk(16, 16);

    rowcount_kernel<<<1, 1024>>>(protok);
    copy_kernel<<<2048, 256>>>(px, x_in, XN);

    for (int l = 0; l < NLAYERS; l++) {
        gemm_tf32<<<dim3(4, 32),  256>>>(px,   wq_w, wq_b, nullptr, pq, BB*SS, DD,   DD,   0, 1);
        gemm_tf32<<<dim3(4, 32),  256>>>(px,   wk_w, wk_b, nullptr, pk, BB*SS, DD,   DD,   0, 1);
        gemm_tf32<<<dim3(4, 32),  256>>>(px,   wv_w, wv_b, nullptr, pv, BB*SS, DD,   DD,   0, 1);
        init_reduce_kernel<<<1, 64>>>();
        logits_kernel<<<dim3(16, 16, 32), blk>>>(mask);
        exp_kernel<<<dim3(64, 32), 256>>>();
        attv_kernel<<<dim3(16, 1, 32), blk>>>();
        gemm_tf32<<<dim3(4, 32),  256>>>(patt, wo_w, wo_b, px,      py, BB*SS, DD,   DD,   0, 0);
        ln_kernel<<<BB*SS, 128>>>(py, ln1g, ln1b, po1);
        gemm_tf32<<<dim3(16, 32), 256>>>(po1,  w1,   b1,   nullptr, ph, BB*SS, DFFN, DD,   1, 0);
        gemm_tf32<<<dim3(4, 32),  256>>>(ph,   w2,   b2,   po1,     py, BB*SS, DD,   DFFN, 0, 0);
        ln_kernel<<<BB*SS, 128>>>(py, ln2g, ln2b, px);
    }

    if (out_size >= XN) {
        copy_kernel<<<2048, 256>>>((float*)d_out, px, XN);
    }
    if (out_size >= XN + AWN) {
        awout_kernel<<<AWN / 256, 256>>>((float*)d_out + XN);
    }
}

// round 4
// speedup vs baseline: 2.6429x; 1.8933x over previous
#include <cuda_runtime.h>
#include <math.h>
#include <stdint.h>

#define BB      4
#define SS      1024
#define DD      512
#define HH      8
#define DEP     64
#define DFFN    2048
#define NLAYERS 4

#define XN  (BB*SS*DD)       /* 2097152  */
#define AWN (BB*HH*SS*SS)    /* 33554432 */

// ---------------- device scratch (no allocation allowed) ----------------
__device__ float g_x   [XN];
__device__ float g_q   [XN];
__device__ float g_k   [XN];
__device__ float g_v   [XN];
__device__ float g_att [XN];
__device__ float g_y   [XN];
__device__ float g_o1  [XN];
__device__ float g_hbuf[BB*SS*DFFN];
__device__ float g_e   [AWN];          // logits, then exp(logits - max), in place
__device__ int   g_maxbits[BB*HH];
__device__ float g_sum    [BB*HH];
__device__ float g_rowcount;

// ---------------- helpers ----------------
__device__ __forceinline__ int f2o(float f) {
    int i = __float_as_int(f);
    return (i >= 0) ? i : (i ^ 0x7FFFFFFF);
}
__device__ __forceinline__ float o2f(int i) {
    return __int_as_float((i >= 0) ? i : (i ^ 0x7FFFFFFF));
}
__device__ __forceinline__ uint32_t f2tf(float f) {
    uint32_t u;
    asm("cvt.rna.tf32.f32 %0, %1;" : "=r"(u) : "f"(f));
    return u;
}
__device__ __forceinline__ void mma_tf32(float* c, const uint32_t* a, const uint32_t* b) {
    asm volatile(
        "mma.sync.aligned.m16n8k8.row.col.f32.tf32.tf32.f32 "
        "{%0,%1,%2,%3}, {%4,%5,%6,%7}, {%8,%9}, {%0,%1,%2,%3};\n"
        : "+f"(c[0]), "+f"(c[1]), "+f"(c[2]), "+f"(c[3])
        : "r"(a[0]), "r"(a[1]), "r"(a[2]), "r"(a[3]), "r"(b[0]), "r"(b[1]));
}

// ---------------- row_count = count_nonzero(protok[0, :]) ----------------
__global__ void rowcount_kernel(const int* __restrict__ protok) {
    __shared__ int red[32];
    int t = threadIdx.x;                 // 1024 threads
    int c = (protok[t] != 0) ? 1 : 0;
    #pragma unroll
    for (int o = 16; o; o >>= 1) c += __shfl_xor_sync(0xffffffffu, c, o);
    if ((t & 31) == 0) red[t >> 5] = c;
    __syncthreads();
    if (t < 32) {
        int v = red[t];
        #pragma unroll
        for (int o = 16; o; o >>= 1) v += __shfl_xor_sync(0xffffffffu, v, o);
        if (t == 0) g_rowcount = (float)v;
    }
}

__global__ void init_reduce_kernel() {
    int t = threadIdx.x;
    if (t < BB * HH) { g_maxbits[t] = (int)0x80000000; g_sum[t] = 0.0f; }
}

__global__ void copy_kernel(float* __restrict__ dst, const float* __restrict__ src, int n) {
    int i = blockIdx.x * blockDim.x + threadIdx.x;
    int stride = gridDim.x * blockDim.x;
    for (; i < n; i += stride) dst[i] = src[i];
}

// ================= tf32 tensor-core GEMM: C = A[M,K] @ W[K,N] =================
// 128x64 block tile, 8 warps (warp tile 32x32), k-chunk 32, m16n8k8 HMMA (1x tf32).
// Epilogue fuses +bias, +residual, relu, head-split scatter.
#define KC 32
#define APITCH 36    /* (36r + tg)%32 = (4r+tg)%32 -> conflict-free */
#define BPITCH 72    /* (72tg + g)%32 = (8tg+g)%32 -> conflict-free */

__global__ __launch_bounds__(256) void gemm_tf32(
    const float* __restrict__ A, const float* __restrict__ W,
    const float* __restrict__ bias, const float* __restrict__ R,
    float* __restrict__ C, int M, int N, int K, int relu, int headsplit)
{
    __shared__ uint32_t As[128 * APITCH];
    __shared__ uint32_t Bs[KC * BPITCH];

    int tid  = threadIdx.x;
    int warp = tid >> 5, lane = tid & 31;
    int wm = (warp & 3) << 5;      // warp m offset: 0/32/64/96
    int wn = (warp >> 2) << 5;     // warp n offset: 0/32
    int g  = lane >> 2, tg = lane & 3;

    int m0 = blockIdx.y << 7, n0 = blockIdx.x << 6;

    int arow = tid >> 3, acol = (tid & 7) << 2;    // A: 128 x 32
    int brow = tid >> 4, bcol = (tid & 15) << 2;   // B: 32 x 64

    float acc[2][4][4];
    #pragma unroll
    for (int i = 0; i < 2; i++)
        #pragma unroll
        for (int j = 0; j < 4; j++)
            #pragma unroll
            for (int r = 0; r < 4; r++) acc[i][j][r] = 0.0f;

    for (int k0 = 0; k0 < K; k0 += KC) {
        #pragma unroll
        for (int i = 0; i < 4; i++) {
            int r = arow + (i << 5);
            float4 v = *(const float4*)&A[(size_t)(m0 + r) * K + k0 + acol];
            uint32_t* p = &As[r * APITCH + acol];
            p[0] = f2tf(v.x); p[1] = f2tf(v.y); p[2] = f2tf(v.z); p[3] = f2tf(v.w);
        }
        #pragma unroll
        for (int i = 0; i < 2; i++) {
            int r = brow + (i << 4);
            float4 v = *(const float4*)&W[(size_t)(k0 + r) * N + n0 + bcol];
            uint32_t* p = &Bs[r * BPITCH + bcol];
            p[0] = f2tf(v.x); p[1] = f2tf(v.y); p[2] = f2tf(v.z); p[3] = f2tf(v.w);
        }
        __syncthreads();

        #pragma unroll
        for (int kk = 0; kk < KC; kk += 8) {
            uint32_t af[2][4];
            #pragma unroll
            for (int mt = 0; mt < 2; mt++) {
                int r = wm + (mt << 4) + g;
                af[mt][0] = As[r * APITCH + kk + tg];
                af[mt][1] = As[(r + 8) * APITCH + kk + tg];
                af[mt][2] = As[r * APITCH + kk + tg + 4];
                af[mt][3] = As[(r + 8) * APITCH + kk + tg + 4];
            }
            uint32_t bf[4][2];
            #pragma unroll
            for (int nt = 0; nt < 4; nt++) {
                int cc = wn + (nt << 3) + g;
                bf[nt][0] = Bs[(kk + tg) * BPITCH + cc];
                bf[nt][1] = Bs[(kk + tg + 4) * BPITCH + cc];
            }
            #pragma unroll
            for (int mt = 0; mt < 2; mt++)
                #pragma unroll
                for (int nt = 0; nt < 4; nt++)
                    mma_tf32(acc[mt][nt], af[mt], bf[nt]);
        }
        __syncthreads();
    }

    #pragma unroll
    for (int mt = 0; mt < 2; mt++) {
        #pragma unroll
        for (int nt = 0; nt < 4; nt++) {
            int n = n0 + wn + (nt << 3) + (tg << 1);
            #pragma unroll
            for (int half = 0; half < 2; half++) {
                int mm = m0 + wm + (mt << 4) + g + half * 8;
                float2 v;
                v.x = acc[mt][nt][half * 2 + 0] + bias[n];
                v.y = acc[mt][nt][half * 2 + 1] + bias[n + 1];
                if (R) {
                    const float2 rr = *(const float2*)&R[(size_t)mm * N + n];
                    v.x += rr.x; v.y += rr.y;
                }
                if (relu) { v.x = fmaxf(v.x, 0.0f); v.y = fmaxf(v.y, 0.0f); }
                if (headsplit) {
                    int bb = mm >> 10, s = mm & 1023, hh = n >> 6, dd = n & 63;
                    *(float2*)&C[(((size_t)(bb * HH + hh) << 10) | (size_t)s) * DEP + dd] = v;
                } else {
                    *(float2*)&C[(size_t)mm * N + n] = v;
                }
            }
        }
    }
}

// ========== logits (tf32x3): per (b,h): (Q K^T + mask*-1e9)/8, fused block-max ==========
// C[i,j] tile 128(i) x 64(j), 8 warps 4x2, warp tile 32x32, KC=32 over DEP=64.
__global__ __launch_bounds__(256) void logits_mma(const float* __restrict__ mask) {
    __shared__ float Qs[128 * APITCH];
    __shared__ float Ks[64 * APITCH];
    __shared__ float red[8];

    int tid  = threadIdx.x;
    int warp = tid >> 5, lane = tid & 31;
    int wm = (warp & 3) << 5;
    int wn = (warp >> 2) << 5;
    int g  = lane >> 2, tg = lane & 3;

    int bh = blockIdx.z; int bi = bh >> 3;
    int i0 = blockIdx.y << 7, j0 = blockIdx.x << 6;
    const float* q = g_q + (size_t)bh * SS * DEP;
    const float* k = g_k + (size_t)bh * SS * DEP;

    int arow = tid >> 3, acol = (tid & 7) << 2;

    float acc[2][4][4];
    #pragma unroll
    for (int i = 0; i < 2; i++)
        #pragma unroll
        for (int j = 0; j < 4; j++)
            #pragma unroll
            for (int r = 0; r < 4; r++) acc[i][j][r] = 0.0f;

    for (int k0 = 0; k0 < DEP; k0 += KC) {
        #pragma unroll
        for (int i = 0; i < 4; i++) {
            int r = arow + (i << 5);
            *(float4*)&Qs[r * APITCH + acol] = *(const float4*)&q[(size_t)(i0 + r) * DEP + k0 + acol];
        }
        #pragma unroll
        for (int i = 0; i < 2; i++) {
            int r = arow + (i << 5);
            *(float4*)&Ks[r * APITCH + acol] = *(const float4*)&k[(size_t)(j0 + r) * DEP + k0 + acol];
        }
        __syncthreads();

        #pragma unroll
        for (int kk = 0; kk < KC; kk += 8) {
            float a32[2][4]; float b32[4][2];
            #pragma unroll
            for (int mt = 0; mt < 2; mt++) {
                int r = wm + (mt << 4) + g;
                a32[mt][0] = Qs[r * APITCH + kk + tg];
                a32[mt][1] = Qs[(r + 8) * APITCH + kk + tg];
                a32[mt][2] = Qs[r * APITCH + kk + tg + 4];
                a32[mt][3] = Qs[(r + 8) * APITCH + kk + tg + 4];
            }
            #pragma unroll
            for (int nt = 0; nt < 4; nt++) {
                int cc = wn + (nt << 3) + g;
                b32[nt][0] = Ks[cc * APITCH + kk + tg];
                b32[nt][1] = Ks[cc * APITCH + kk + tg + 4];
            }
            uint32_t ahi[2][4], alo[2][4], bhi[4][2], blo[4][2];
            #pragma unroll
            for (int mt = 0; mt < 2; mt++)
                #pragma unroll
                for (int r = 0; r < 4; r++) {
                    ahi[mt][r] = f2tf(a32[mt][r]);
                    alo[mt][r] = f2tf(a32[mt][r] - __uint_as_float(ahi[mt][r]));
                }
            #pragma unroll
            for (int nt = 0; nt < 4; nt++)
                #pragma unroll
                for (int r = 0; r < 2; r++) {
                    bhi[nt][r] = f2tf(b32[nt][r]);
                    blo[nt][r] = f2tf(b32[nt][r] - __uint_as_float(bhi[nt][r]));
                }
            #pragma unroll
            for (int mt = 0; mt < 2; mt++)
                #pragma unroll
                for (int nt = 0; nt < 4; nt++) {
                    mma_tf32(acc[mt][nt], alo[mt], bhi[nt]);
                    mma_tf32(acc[mt][nt], ahi[mt], blo[nt]);
                    mma_tf32(acc[mt][nt], ahi[mt], bhi[nt]);
                }
        }
        __syncthreads();
    }

    float* out = g_e + (size_t)bh * SS * SS;
    float lmax = -INFINITY;
    #pragma unroll
    for (int mt = 0; mt < 2; mt++) {
        #pragma unroll
        for (int nt = 0; nt < 4; nt++) {
            int j = j0 + wn + (nt << 3) + (tg << 1);
            #pragma unroll
            for (int half = 0; half < 2; half++) {
                int i = i0 + wm + (mt << 4) + g + half * 8;
                const float2 mk = *(const float2*)&mask[((size_t)bi * SS + i) * SS + j];
                float2 v;
                v.x = (acc[mt][nt][half * 2 + 0] + mk.x * (-1e9f)) * 0.125f;
                v.y = (acc[mt][nt][half * 2 + 1] + mk.y * (-1e9f)) * 0.125f;
                *(float2*)&out[(size_t)i * SS + j] = v;
                lmax = fmaxf(lmax, fmaxf(v.x, v.y));
            }
        }
    }
    #pragma unroll
    for (int o = 16; o; o >>= 1) lmax = fmaxf(lmax, __shfl_xor_sync(0xffffffffu, lmax, o));
    if (lane == 0) red[warp] = lmax;
    __syncthreads();
    if (tid == 0) {
        float m = red[0];
        #pragma unroll
        for (int w = 1; w < 8; w++) m = fmaxf(m, red[w]);
        atomicMax(&g_maxbits[bh], f2o(m));
    }
}

// ---------------- exp in place + partial sums ----------------
__global__ __launch_bounds__(256) void exp_kernel() {
    __shared__ float red[8];
    int bh = blockIdx.y;
    float mx = o2f(g_maxbits[bh]);
    size_t base = (size_t)bh * SS * SS + (size_t)blockIdx.x * 16384;
    int t = threadIdx.x;
    float lsum = 0.0f;
    #pragma unroll
    for (int i = 0; i < 64; i++) {
        size_t idx = base + t + 256 * i;
        float e = expf(g_e[idx] - mx);
        g_e[idx] = e;
        lsum += e;
    }
    #pragma unroll
    for (int o = 16; o; o >>= 1) lsum += __shfl_xor_sync(0xffffffffu, lsum, o);
    if ((t & 31) == 0) red[t >> 5] = lsum;
    __syncthreads();
    if (t == 0) {
        float s = 0.0f;
        #pragma unroll
        for (int w = 0; w < 8; w++) s += red[w];
        atomicAdd(&g_sum[bh], s);
    }
}

// ========== attv (tf32x3): out[b,h,j,d] = (rc/Z) * sum_i E[i,j] V[i,d] ==========
// Tile 128(j) x 64(d); A = E^T (transposed smem access), B = V. i-chunks of 32.
#define EPITCH 136   /* (136tg + g)%32 = (8tg+g)%32 -> conflict-free */
__global__ __launch_bounds__(256) void attv_mma() {
    __shared__ float Es[KC * EPITCH];
    __shared__ float Vs[KC * BPITCH];

    int tid  = threadIdx.x;
    int warp = tid >> 5, lane = tid & 31;
    int wm = (warp & 3) << 5;      // j quadrant
    int wn = (warp >> 2) << 5;     // d half
    int g  = lane >> 2, tg = lane & 3;

    int bh = blockIdx.y; int bat = bh >> 3, hh = bh & 7;
    int j0 = blockIdx.x << 7;
    const float* e = g_e + (size_t)bh * SS * SS;
    const float* v = g_v + (size_t)bh * SS * DEP;

    int erow = tid >> 5, ecol = (tid & 31) << 2;   // E: 32 x 128
    int vrow = tid >> 4, vcol = (tid & 15) << 2;   // V: 32 x 64

    float acc[2][4][4];
    #pragma unroll
    for (int i = 0; i < 2; i++)
        #pragma unroll
        for (int j = 0; j < 4; j++)
            #pragma unroll
            for (int r = 0; r < 4; r++) acc[i][j][r] = 0.0f;

    for (int i0 = 0; i0 < SS; i0 += KC) {
        #pragma unroll
        for (int i = 0; i < 4; i++) {
            int r = erow + (i << 3);
            *(float4*)&Es[r * EPITCH + ecol] = *(const float4*)&e[(size_t)(i0 + r) * SS + j0 + ecol];
        }
        #pragma unroll
        for (int i = 0; i < 2; i++) {
            int r = vrow + (i << 4);
            *(float4*)&Vs[r * BPITCH + vcol] = *(const float4*)&v[(size_t)(i0 + r) * DEP + vcol];
        }
        __syncthreads();

        #pragma unroll
        for (int kk = 0; kk < KC; kk += 8) {
            float a32[2][4]; float b32[4][2];
            #pragma unroll
            for (int mt = 0; mt < 2; mt++) {
                int r = wm + (mt << 4) + g;       // j index within tile
                a32[mt][0] = Es[(kk + tg) * EPITCH + r];
                a32[mt][1] = Es[(kk + tg) * EPITCH + r + 8];
                a32[mt][2] = Es[(kk + tg + 4) * EPITCH + r];
                a32[mt][3] = Es[(kk + tg + 4) * EPITCH + r + 8];
            }
            #pragma unroll
            for (int nt = 0; nt < 4; nt++) {
                int cc = wn + (nt << 3) + g;      // d index
                b32[nt][0] = Vs[(kk + tg) * BPITCH + cc];
                b32[nt][1] = Vs[(kk + tg + 4) * BPITCH + cc];
            }
            uint32_t ahi[2][4], alo[2][4], bhi[4][2], blo[4][2];
            #pragma unroll
            for (int mt = 0; mt < 2; mt++)
                #pragma unroll
                for (int r = 0; r < 4; r++) {
                    ahi[mt][r] = f2tf(a32[mt][r]);
                    alo[mt][r] = f2tf(a32[mt][r] - __uint_as_float(ahi[mt][r]));
                }
            #pragma unroll
            for (int nt = 0; nt < 4; nt++)
                #pragma unroll
                for (int r = 0; r < 2; r++) {
                    bhi[nt][r] = f2tf(b32[nt][r]);
                    blo[nt][r] = f2tf(b32[nt][r] - __uint_as_float(bhi[nt][r]));
                }
            #pragma unroll
            for (int mt = 0; mt < 2; mt++)
                #pragma unroll
                for (int nt = 0; nt < 4; nt++) {
                    mma_tf32(acc[mt][nt], alo[mt], bhi[nt]);
                    mma_tf32(acc[mt][nt], ahi[mt], blo[nt]);
                    mma_tf32(acc[mt][nt], ahi[mt], bhi[nt]);
                }
        }
        __syncthreads();
    }

    float scale = g_rowcount / g_sum[bh];
    #pragma unroll
    for (int mt = 0; mt < 2; mt++) {
        #pragma unroll
        for (int nt = 0; nt < 4; nt++) {
            int d = wn + (nt << 3) + (tg << 1);
            #pragma unroll
            for (int half = 0; half < 2; half++) {
                int j = j0 + wm + (mt << 4) + g + half * 8;
                float2 o;
                o.x = acc[mt][nt][half * 2 + 0] * scale;
                o.y = acc[mt][nt][half * 2 + 1] * scale;
                *(float2*)&g_att[((size_t)bat * SS + j) * DD + hh * DEP + d] = o;
            }
        }
    }
}

// ---------------- LayerNorm over last dim (512), eps inside sqrt ----------------
__global__ __launch_bounds__(128) void ln_kernel(
    const float* __restrict__ in, const float* __restrict__ gam,
    const float* __restrict__ bet, float* __restrict__ out)
{
    __shared__ float red[4];
    __shared__ float bc;
    int row = blockIdx.x, t = threadIdx.x;
    const float* rp = in + (size_t)row * DD;
    float v0 = rp[t], v1 = rp[t + 128], v2 = rp[t + 256], v3 = rp[t + 384];
    float s = v0 + v1 + v2 + v3;
    #pragma unroll
    for (int o = 16; o; o >>= 1) s += __shfl_xor_sync(0xffffffffu, s, o);
    if ((t & 31) == 0) red[t >> 5] = s;
    __syncthreads();
    if (t == 0) bc = (red[0] + red[1] + red[2] + red[3]) * (1.0f / 512.0f);
    __syncthreads();
    float mean = bc;
    float d0 = v0 - mean, d1 = v1 - mean, d2 = v2 - mean, d3 = v3 - mean;
    float ss = d0 * d0 + d1 * d1 + d2 * d2 + d3 * d3;
    #pragma unroll
    for (int o = 16; o; o >>= 1) ss += __shfl_xor_sync(0xffffffffu, ss, o);
    __syncthreads();
    if ((t & 31) == 0) red[t >> 5] = ss;
    __syncthreads();
    if (t == 0) bc = (red[0] + red[1] + red[2] + red[3]) * (1.0f / 512.0f);
    __syncthreads();
    float inv = rsqrtf(bc + 1e-9f);
    float* op = out + (size_t)row * DD;
    op[t]       = gam[t]       * d0 * inv + bet[t];
    op[t + 128] = gam[t + 128] * d1 * inv + bet[t + 128];
    op[t + 256] = gam[t + 256] * d2 * inv + bet[t + 256];
    op[t + 384] = gam[t + 384] * d3 * inv + bet[t + 384];
}

// ---------------- final aw write: normalized * row_count ----------------
__global__ __launch_bounds__(256) void awout_kernel(float* __restrict__ out) {
    size_t i = (size_t)blockIdx.x * 256 + threadIdx.x;
    int bh = (int)(i >> 20);                   // S*S = 2^20
    out[i] = g_e[i] * (g_rowcount / g_sum[bh]);
}

// ---------------- launch ----------------
extern "C" void kernel_launch(void* const* d_in, const int* in_sizes, int n_in,
                              void* d_out, int out_size)
{
    const float* x_in  = (const float*)d_in[0];
    const float* mask  = (const float*)d_in[1];
    const int*   protok= (const int*)  d_in[2];
    const float* wq_w  = (const float*)d_in[3];
    const float* wq_b  = (const float*)d_in[4];
    const float* wk_w  = (const float*)d_in[5];
    const float* wk_b  = (const float*)d_in[6];
    const float* wv_w  = (const float*)d_in[7];
    const float* wv_b  = (const float*)d_in[8];
    const float* wo_w  = (const float*)d_in[9];
    const float* wo_b  = (const float*)d_in[10];
    const float* w1    = (const float*)d_in[11];
    const float* b1    = (const float*)d_in[12];
    const float* w2    = (const float*)d_in[13];
    const float* b2    = (const float*)d_in[14];
    const float* ln1g  = (const float*)d_in[15];
    const float* ln1b  = (const float*)d_in[16];
    const float* ln2g  = (const float*)d_in[17];
    const float* ln2b  = (const float*)d_in[18];

    float *px, *pq, *pk, *pv, *patt, *py, *po1, *ph;
    cudaGetSymbolAddress((void**)&px,   g_x);
    cudaGetSymbolAddress((void**)&pq,   g_q);
    cudaGetSymbolAddress((void**)&pk,   g_k);
    cudaGetSymbolAddress((void**)&pv,   g_v);
    cudaGetSymbolAddress((void**)&patt, g_att);
    cudaGetSymbolAddress((void**)&py,   g_y);
    cudaGetSymbolAddress((void**)&po1,  g_o1);
    cudaGetSymbolAddress((void**)&ph,   g_hbuf);

    rowcount_kernel<<<1, 1024>>>(protok);
    copy_kernel<<<2048, 256>>>(px, x_in, XN);

    for (int l = 0; l < NLAYERS; l++) {
        gemm_tf32<<<dim3(8, 32),  256>>>(px,   wq_w, wq_b, nullptr, pq, BB*SS, DD,   DD,   0, 1);
        gemm_tf32<<<dim3(8, 32),  256>>>(px,   wk_w, wk_b, nullptr, pk, BB*SS, DD,   DD,   0, 1);
        gemm_tf32<<<dim3(8, 32),  256>>>(px,   wv_w, wv_b, nullptr, pv, BB*SS, DD,   DD,   0, 1);
        init_reduce_kernel<<<1, 64>>>();
        logits_mma<<<dim3(16, 8, 32), 256>>>(mask);
        exp_kernel<<<dim3(64, 32), 256>>>();
        attv_mma<<<dim3(8, 32), 256>>>();
        gemm_tf32<<<dim3(8, 32),  256>>>(patt, wo_w, wo_b, px,      py, BB*SS, DD,   DD,   0, 0);
        ln_kernel<<<BB*SS, 128>>>(py, ln1g, ln1b, po1);
        gemm_tf32<<<dim3(32, 32), 256>>>(po1,  w1,   b1,   nullptr, ph, BB*SS, DFFN, DD,   1, 0);
        gemm_tf32<<<dim3(8, 32),  256>>>(ph,   w2,   b2,   po1,     py, BB*SS, DD,   DFFN, 0, 0);
        ln_kernel<<<BB*SS, 128>>>(py, ln2g, ln2b, px);
    }

    if (out_size >= XN) {
        copy_kernel<<<2048, 256>>>((float*)d_out, px, XN);
    }
    if (out_size >= XN + AWN) {
        awout_kernel<<<AWN / 256, 256>>>((float*)d_out + XN);
    }
}